// round 12
// baseline (speedup 1.0000x reference)
#include <cuda_runtime.h>
#include <cuda_fp16.h>
#include <cstdint>

typedef unsigned long long u64;

#define Bn 256
#define Tn 256
#define Sn 20
#define NROWS (Bn*Tn)   // 65536

// zx[row][u*4+g] (gate-major float4 per unit) = h_inner[row] @ Wo + bo, permuted
__device__ float g_zx[NROWS * 96];
__device__ __align__(16) unsigned char g_btiles[32768];  // Bh|Bl fp16, swizzled

// ---------- packed f32x2 helpers (outer kernel) ----------
__device__ __forceinline__ u64 ffma2(u64 a, u64 b, u64 c){
    u64 d;
    asm("fma.rn.f32x2 %0, %1, %2, %3;" : "=l"(d) : "l"(a), "l"(b), "l"(c));
    return d;
}
__device__ __forceinline__ u64 add2(u64 a, u64 b){
    u64 d;
    asm("add.rn.f32x2 %0, %1, %2;" : "=l"(d) : "l"(a), "l"(b));
    return d;
}
__device__ __forceinline__ u64 pk2(float lo, float hi){
    u64 r; asm("mov.b64 %0, {%1, %2};" : "=l"(r) : "f"(lo), "f"(hi)); return r;
}
__device__ __forceinline__ void up2(u64 v, float& lo, float& hi){
    asm("mov.b64 {%0, %1}, %2;" : "=f"(lo), "=f"(hi) : "l"(v));
}

// ---------- activations ----------
__device__ __forceinline__ float tanha(float x){
    float r; asm("tanh.approx.f32 %0, %1;" : "=f"(r) : "f"(x)); return r;
}
__device__ __forceinline__ float sigt(float x){
    return fmaf(0.5f, tanha(0.5f * x), 0.5f);
}

// ---------- smem / swizzle ----------
__device__ __forceinline__ uint32_t smem_to_u32(const void* p){
    uint32_t a;
    asm("{ .reg .u64 t; cvta.to.shared.u64 t, %1; cvt.u32.u64 %0, t; }"
        : "=r"(a) : "l"(p));
    return a;
}
#define SWZ(bo) ((bo) ^ (((bo) >> 3) & 0x70))

// ---------- mma.sync / ldmatrix (fp16, baseline PTX) ----------
#define MMA_F16(d, a, b0v, b1v) \
    asm volatile("mma.sync.aligned.m16n8k16.row.col.f32.f16.f16.f32 " \
        "{%0,%1,%2,%3}, {%4,%5,%6,%7}, {%8,%9}, {%0,%1,%2,%3};" \
        : "+f"((d)[0]), "+f"((d)[1]), "+f"((d)[2]), "+f"((d)[3]) \
        : "r"((a)[0]), "r"((a)[1]), "r"((a)[2]), "r"((a)[3]), "r"(b0v), "r"(b1v))

#define LDSM4(r, addr) \
    asm volatile("ldmatrix.sync.aligned.m8n8.x4.shared.b16 {%0,%1,%2,%3}, [%4];" \
        : "=r"((r)[0]), "=r"((r)[1]), "=r"((r)[2]), "=r"((r)[3]) : "r"(addr))

// SMEM layout (bytes)
#define OFF_AH 0        // A hi [64][64] fp16, 8KB
#define OFF_AL 8192     // A lo, 8KB
#define OFF_BH 16384    // B hi [128][64] fp16, 16KB (Wo fp32 reused here post-loop)
#define OFF_BL 32768    // B lo, 16KB
#define OFF_BO 49152    // bo, 96 f32
#define SMEM_SZ 49664

// =====================================================================
// B-tile prep: loop-invariant weight tiles (fp16 hi/lo, SW128-swizzled).
// n-row = permuted gate col ([i,f]x32u | [g,o]x32u), k = [Ui | Wi | bi | 0].
// =====================================================================
__global__ void bprep(const float* __restrict__ Wi,
                      const float* __restrict__ Ui,
                      const float* __restrict__ bi)
{
    int idx = blockIdx.x * 256 + threadIdx.x;
    if (idx >= 8192) return;
    int n = idx >> 6, k = idx & 63;
    int u, g;
    if (n < 64){ u = n >> 1; g = n & 1; }
    else       { u = (n - 64) >> 1; g = 2 + (n & 1); }
    int col = g * 32 + u;
    float w = 0.f;
    if (k < 32)       w = Ui[k * 128 + col];
    else if (k == 32) w = Wi[col];
    else if (k == 33) w = bi[col];
    __half wh = __float2half(w);
    __half wl = __float2half(w - __half2float(wh));
    uint32_t off = SWZ((uint32_t)(n * 128 + k * 2));
    *(__half*)(g_btiles + off)         = wh;
    *(__half*)(g_btiles + 16384 + off) = wl;
}

// =====================================================================
// Inner LSTM via warp-level fp16 mma.sync. 1024 blocks x 128 thr (4 warps),
// 64 rows/block. Warp w owns rows 16w..16w+15 (no block sync in loop).
// Per step: D[16x128] = A[16x48] x B[48x128], 3-product fp16 hi/lo split.
// Epilogue writes zx GATE-MAJOR ([u*4+g]) so the outer reads one coalesced
// float4 per lane per step.
// =====================================================================
__global__ void __launch_bounds__(128, 4) inner_mma(
    const float* __restrict__ x,
    const float* __restrict__ Wo, const float* __restrict__ bo)
{
    extern __shared__ char smc[];
    const uint32_t sb = smem_to_u32(smc);
    const int tid  = threadIdx.x;
    const int wid  = tid >> 5;
    const int lane = tid & 31;
    const int q    = lane & 3;
    const int rr   = lane >> 2;            // 0..7
    const int wrow0 = wid * 16;            // warp's first local row (0..48)

    // --- copy prebuilt B tiles (32KB contiguous: BH then BL) ---
    {
        const uint4* src = (const uint4*)g_btiles;
        uint4* dst = (uint4*)(smc + OFF_BH);
        for (int i = tid; i < 2048; i += 128) dst[i] = src[i];
    }
    // --- zero A tiles (h0=0, pads=0): 16KB = 4096 u32 ---
    for (int i = tid; i < 4096; i += 128)
        ((uint32_t*)(smc + OFF_AH))[i] = 0u;
    // --- stage bo ---
    if (tid < 96) ((float*)(smc + OFF_BO))[tid] = bo[tid];
    __syncthreads();

    // --- loop-invariant ldmatrix addressing (FULL swizzle per (lane,kc)) ---
    const uint32_t aRow  = wrow0 + (lane & 15);
    const uint32_t aByte = (uint32_t)(lane >> 4) << 4;
    const uint32_t aMask = (aRow & 7) << 4;
    const uint32_t aBase = sb + OFF_AH + aRow * 128;
    uint32_t akOff[3];
    #pragma unroll
    for (int kc = 0; kc < 3; kc++)
        akOff[kc] = (aByte + 32u * kc) ^ aMask;    // < 128, exact SW128

    uint32_t bBase[8];
    uint32_t bkOff[3];
    {
        uint32_t nrow = ((uint32_t)(lane >> 4) << 3) + (lane & 7);
        uint32_t bbyte = ((uint32_t)((lane >> 3) & 1)) << 4;
        uint32_t bMask = (nrow & 7) << 4;
        #pragma unroll
        for (int np = 0; np < 8; np++)
            bBase[np] = sb + OFF_BH + (16 * np + nrow) * 128;
        #pragma unroll
        for (int kc = 0; kc < 3; kc++)
            bkOff[kc] = (bbyte + 32u * kc) ^ bMask;
    }
    const uint32_t xoff = SWZ((uint32_t)((wrow0 + (lane & 15)) * 128 + 64));

    const long grow = (long)blockIdx.x * 64 + wrow0 + (lane & 15);
    const float* xrow = x + grow * Sn;
    float xnext = __ldg(xrow);

    float cst[16];
    #pragma unroll
    for (int i = 0; i < 16; i++) cst[i] = 0.f;

    const int row0 = wrow0 + rr;
    const int row1 = row0 + 8;

    #pragma unroll 1
    for (int s = 0; s < Sn; s++){
        if (lane < 16){
            float xv = xnext;
            int sp = (s + 1 < Sn) ? s + 1 : s;
            xnext = __ldg(xrow + sp);
            __half xh = __float2half(xv);
            __half xl = __float2half(xv - __half2float(xh));
            uint32_t hi = (0x3C00u << 16) | (uint32_t)__half_as_ushort(xh);
            uint32_t lo = (uint32_t)__half_as_ushort(xl);
            *(uint32_t*)(smc + OFF_AH + xoff) = hi;
            *(uint32_t*)(smc + OFF_AL + xoff) = lo;
        }
        __syncwarp();

        uint32_t ah[3][4], al[3][4];
        #pragma unroll
        for (int kc = 0; kc < 3; kc++){
            LDSM4(ah[kc], aBase + akOff[kc]);
            LDSM4(al[kc], aBase + 8192 + akOff[kc]);
        }
        __syncwarp();

        #pragma unroll
        for (int npp = 0; npp < 4; npp++){
            float dIF0[4] = {0.f,0.f,0.f,0.f};
            float dIF1[4] = {0.f,0.f,0.f,0.f};
            float dGO0[4] = {0.f,0.f,0.f,0.f};
            float dGO1[4] = {0.f,0.f,0.f,0.f};
            #pragma unroll
            for (int kc = 0; kc < 3; kc++){
                uint32_t bIFh[4], bIFl[4], bGOh[4], bGOl[4];
                LDSM4(bIFh, bBase[npp]     + bkOff[kc]);
                LDSM4(bIFl, bBase[npp]     + 16384 + bkOff[kc]);
                LDSM4(bGOh, bBase[npp + 4] + bkOff[kc]);
                LDSM4(bGOl, bBase[npp + 4] + 16384 + bkOff[kc]);
                MMA_F16(dIF0, ah[kc], bIFh[0], bIFh[1]);
                MMA_F16(dIF0, ah[kc], bIFl[0], bIFl[1]);
                MMA_F16(dIF0, al[kc], bIFh[0], bIFh[1]);
                MMA_F16(dIF1, ah[kc], bIFh[2], bIFh[3]);
                MMA_F16(dIF1, ah[kc], bIFl[2], bIFl[3]);
                MMA_F16(dIF1, al[kc], bIFh[2], bIFh[3]);
                MMA_F16(dGO0, ah[kc], bGOh[0], bGOh[1]);
                MMA_F16(dGO0, ah[kc], bGOl[0], bGOl[1]);
                MMA_F16(dGO0, al[kc], bGOh[0], bGOh[1]);
                MMA_F16(dGO1, ah[kc], bGOh[2], bGOh[3]);
                MMA_F16(dGO1, ah[kc], bGOl[2], bGOl[3]);
                MMA_F16(dGO1, al[kc], bGOh[2], bGOh[3]);
            }
            const int vA = 8 * npp + q;
            const int vB = vA + 4;
            #pragma unroll
            for (int e = 0; e < 4; e++){
                const float* dif = (e < 2) ? dIF0 : dIF1;
                const float* dgo = (e < 2) ? dGO0 : dGO1;
                int half_ = (e & 1) * 2;
                float zi = dif[half_], zf = dif[half_ + 1];
                float zg = dgo[half_], zo = dgo[half_ + 1];
                float ii = sigt(zi), ff = sigt(zf);
                float gg = tanha(zg), oo = sigt(zo);
                float cv = ff * cst[npp * 4 + e] + ii * gg;
                cst[npp * 4 + e] = cv;
                float h = oo * tanha(cv);
                int v  = (e < 2) ? vA : vB;
                int rw = (e & 1) ? row1 : row0;
                uint32_t off = SWZ((uint32_t)(rw * 128 + v * 2));
                __half hh = __float2half(h);
                __half hl = __float2half(h - __half2float(hh));
                *(__half*)(smc + OFF_AH + off) = hh;
                *(__half*)(smc + OFF_AL + off) = hl;
            }
        }
        __syncwarp();
    }

    // --- zx epilogue: stage Wo (fp32) over the BH region, then GEMV ---
    __syncthreads();
    {
        float4* dst = (float4*)(smc + OFF_BH);
        const float4* src = (const float4*)Wo;   // 32*96 f32 = 768 float4
        for (int i = tid; i < 768; i += 128) dst[i] = src[i];
    }
    __syncthreads();
    {
        const int row = tid >> 1;          // 0..63
        const int cg  = tid & 1;           // natural-col half [cg*48, cg*48+48)
        const float* wos = (float*)(smc + OFF_BH);
        const float* bos = (float*)(smc + OFF_BO);
        float4 acc[12];
        #pragma unroll
        for (int j = 0; j < 12; j++)
            acc[j] = *(const float4*)(bos + cg * 48 + j * 4);
        #pragma unroll 4
        for (int k = 0; k < 32; k++){
            uint32_t off = SWZ((uint32_t)(row * 128 + k * 2));
            float hk = __half2float(*(__half*)(smc + OFF_AH + off))
                     + __half2float(*(__half*)(smc + OFF_AL + off));
            const float4* wp = (const float4*)(wos + k * 96 + cg * 48);
            #pragma unroll
            for (int j = 0; j < 12; j++){
                float4 w = wp[j];
                acc[j].x = fmaf(hk, w.x, acc[j].x);
                acc[j].y = fmaf(hk, w.y, acc[j].y);
                acc[j].z = fmaf(hk, w.z, acc[j].z);
                acc[j].w = fmaf(hk, w.w, acc[j].w);
            }
        }
        // permuted gate-major store: natural col c = gbase*24 + ... -> [u*4+g]
        float* zp = g_zx + ((size_t)blockIdx.x * 64 + row) * 96;
        const int gbase = 2 * cg;
        #pragma unroll
        for (int j = 0; j < 12; j++){
            float v[4] = {acc[j].x, acc[j].y, acc[j].z, acc[j].w};
            #pragma unroll
            for (int m = 0; m < 4; m++){
                int cp = j * 4 + m;                 // 0..47 within half
                int g = gbase + (cp >= 24 ? 1 : 0);
                int u = (cp >= 24) ? cp - 24 : cp;
                zp[u * 4 + g] = v[m];
            }
        }
    }
}

// =====================================================================
// Outer LSTM + dense head: one warp per batch row. Register weights.
// zx gate-major -> ONE coalesced float4 load per lane per step.
// Static depth-4 prefetch (4 named slots, manual 4x unroll, no LDL).
// =====================================================================
__device__ __forceinline__ void outer_step(
    float& h, float& c, float4 z,
    const u64* w_if, const u64* w_go)
{
    u64 a0 = pk2(z.x, z.y), a1 = 0ULL;
    u64 b0 = pk2(z.z, z.w), b1 = 0ULL;
    #pragma unroll
    for (int j = 0; j < 12; j++){
        float h0 = __shfl_sync(0xffffffffu, h, j);
        float h1 = __shfl_sync(0xffffffffu, h, j + 12);
        u64 H0 = pk2(h0, h0), H1 = pk2(h1, h1);
        a0 = ffma2(H0, w_if[j],      a0);
        b0 = ffma2(H0, w_go[j],      b0);
        a1 = ffma2(H1, w_if[j + 12], a1);
        b1 = ffma2(H1, w_go[j + 12], b1);
    }
    u64 zAf = add2(a0, a1);
    u64 zBf = add2(b0, b1);
    float zi, zf, zg, zo;
    up2(zAf, zi, zf);
    up2(zBf, zg, zo);
    float fi = sigt(zi), ff = sigt(zf), gg = tanha(zg), oo = sigt(zo);
    c = fmaf(ff, c, fi * gg);
    h = oo * tanha(c);
}

__global__ void __launch_bounds__(32) outer_kernel(
    const int*   __restrict__ lengths,
    const float* __restrict__ Uo,
    const float* __restrict__ Wd,
    const float* __restrict__ bd,
    float*       __restrict__ out)
{
    const int l  = threadIdx.x;
    const int la = (l < 24) ? l : 0;
    const int b  = blockIdx.x;

    u64 w_if[24], w_go[24];
    #pragma unroll
    for (int k = 0; k < 24; k++){
        const float* row = Uo + k * 96;
        w_if[k] = pk2(__ldg(row + la),      __ldg(row + 24 + la));
        w_go[k] = pk2(__ldg(row + 48 + la), __ldg(row + 72 + la));
    }

    const int len = lengths[b];            // in [1, T]
    // gate-major zx: float4 per (t, unit): index t*24 + la
    const float4* z4 = (const float4*)g_zx + (size_t)b * Tn * 24 + la;

    // static depth-4 prefetch
    float4 P0, P1, P2, P3;
    {
        int t1 = (1 < len) ? 1 : len - 1;
        int t2 = (2 < len) ? 2 : len - 1;
        int t3 = (3 < len) ? 3 : len - 1;
        P0 = __ldg(z4);
        P1 = __ldg(z4 + (size_t)t1 * 24);
        P2 = __ldg(z4 + (size_t)t2 * 24);
        P3 = __ldg(z4 + (size_t)t3 * 24);
    }

    float h = 0.f, c = 0.f;
    int t = 0;
    while (t < len){
        {
            float4 z = P0;
            int tp = (t + 4 < len) ? t + 4 : len - 1;
            P0 = __ldg(z4 + (size_t)tp * 24);
            outer_step(h, c, z, w_if, w_go);
        }
        if (++t >= len) break;
        {
            float4 z = P1;
            int tp = (t + 4 < len) ? t + 4 : len - 1;
            P1 = __ldg(z4 + (size_t)tp * 24);
            outer_step(h, c, z, w_if, w_go);
        }
        if (++t >= len) break;
        {
            float4 z = P2;
            int tp = (t + 4 < len) ? t + 4 : len - 1;
            P2 = __ldg(z4 + (size_t)tp * 24);
            outer_step(h, c, z, w_if, w_go);
        }
        if (++t >= len) break;
        {
            float4 z = P3;
            int tp = (t + 4 < len) ? t + 4 : len - 1;
            P3 = __ldg(z4 + (size_t)tp * 24);
            outer_step(h, c, z, w_if, w_go);
        }
        ++t;
    }

    float p = (l < 24) ? h * __ldg(Wd + la) : 0.f;
    #pragma unroll
    for (int off = 16; off; off >>= 1) p += __shfl_xor_sync(0xffffffffu, p, off);
    if (l == 0) out[b] = fmaf(0.5f, tanha(0.5f * (p + bd[0])), 0.5f);
}

extern "C" void kernel_launch(void* const* d_in, const int* in_sizes, int n_in,
                              void* d_out, int out_size)
{
    const float* x       = (const float*)d_in[0];
    const int*   lengths = (const int*)  d_in[1];
    const float* Wi      = (const float*)d_in[2];
    const float* Ui      = (const float*)d_in[3];
    const float* bi      = (const float*)d_in[4];
    const float* Wo      = (const float*)d_in[5];
    const float* Uo      = (const float*)d_in[6];
    const float* bo      = (const float*)d_in[7];
    const float* Wd      = (const float*)d_in[8];
    const float* bd      = (const float*)d_in[9];
    float* out = (float*)d_out;

    cudaFuncSetAttribute(inner_mma,
                         cudaFuncAttributeMaxDynamicSharedMemorySize, SMEM_SZ);

    bprep<<<32, 256>>>(Wi, Ui, bi);
    inner_mma<<<1024, 128, SMEM_SZ>>>(x, Wo, bo);
    outer_kernel<<<256, 32>>>(lengths, Uo, Wd, bd, out);
}

// round 13
// speedup vs baseline: 1.1302x; 1.1302x over previous
#include <cuda_runtime.h>
#include <cuda_fp16.h>
#include <cstdint>

typedef unsigned long long u64;

#define Bn 256
#define Tn 256
#define Sn 20
#define NROWS (Bn*Tn)   // 65536

__device__ float g_zx[NROWS * 96];   // zx[row][96] = h_inner[row] @ Wo + bo
__device__ __align__(16) unsigned char g_btiles[32768];  // Bh|Bl fp16, swizzled

// ---------- packed f32x2 helpers (outer kernel) ----------
__device__ __forceinline__ u64 ffma2(u64 a, u64 b, u64 c){
    u64 d;
    asm("fma.rn.f32x2 %0, %1, %2, %3;" : "=l"(d) : "l"(a), "l"(b), "l"(c));
    return d;
}
__device__ __forceinline__ u64 add2(u64 a, u64 b){
    u64 d;
    asm("add.rn.f32x2 %0, %1, %2;" : "=l"(d) : "l"(a), "l"(b));
    return d;
}
__device__ __forceinline__ u64 pk2(float lo, float hi){
    u64 r; asm("mov.b64 %0, {%1, %2};" : "=l"(r) : "f"(lo), "f"(hi)); return r;
}
__device__ __forceinline__ void up2(u64 v, float& lo, float& hi){
    asm("mov.b64 {%0, %1}, %2;" : "=f"(lo), "=f"(hi) : "l"(v));
}

// ---------- activations ----------
__device__ __forceinline__ float tanha(float x){
    float r; asm("tanh.approx.f32 %0, %1;" : "=f"(r) : "f"(x)); return r;
}
__device__ __forceinline__ float sigt(float x){
    return fmaf(0.5f, tanha(0.5f * x), 0.5f);
}

// ---------- smem / swizzle ----------
__device__ __forceinline__ uint32_t smem_to_u32(const void* p){
    uint32_t a;
    asm("{ .reg .u64 t; cvta.to.shared.u64 t, %1; cvt.u32.u64 %0, t; }"
        : "=r"(a) : "l"(p));
    return a;
}
#define SWZ(bo) ((bo) ^ (((bo) >> 3) & 0x70))

// ---------- mma.sync / ldmatrix (fp16, baseline PTX) ----------
#define MMA_F16(d, a, b0v, b1v) \
    asm volatile("mma.sync.aligned.m16n8k16.row.col.f32.f16.f16.f32 " \
        "{%0,%1,%2,%3}, {%4,%5,%6,%7}, {%8,%9}, {%0,%1,%2,%3};" \
        : "+f"((d)[0]), "+f"((d)[1]), "+f"((d)[2]), "+f"((d)[3]) \
        : "r"((a)[0]), "r"((a)[1]), "r"((a)[2]), "r"((a)[3]), "r"(b0v), "r"(b1v))

#define LDSM4(r, addr) \
    asm volatile("ldmatrix.sync.aligned.m8n8.x4.shared.b16 {%0,%1,%2,%3}, [%4];" \
        : "=r"((r)[0]), "=r"((r)[1]), "=r"((r)[2]), "=r"((r)[3]) : "r"(addr))

// SMEM layout (bytes)
#define OFF_AH 0        // A hi [64][64] fp16, 8KB
#define OFF_AL 8192     // A lo, 8KB
#define OFF_BH 16384    // B hi [128][64] fp16, 16KB (Wo fp32 reused here post-loop)
#define OFF_BL 32768    // B lo, 16KB
#define OFF_BO 49152    // bo, 96 f32
#define SMEM_SZ 49664

// =====================================================================
// B-tile prep: loop-invariant weight tiles (fp16 hi/lo, SW128-swizzled).
// n-row = permuted gate col ([i,f]x32u | [g,o]x32u), k = [Ui | Wi | bi | 0].
// =====================================================================
__global__ void bprep(const float* __restrict__ Wi,
                      const float* __restrict__ Ui,
                      const float* __restrict__ bi)
{
    int idx = blockIdx.x * 256 + threadIdx.x;
    if (idx >= 8192) return;
    int n = idx >> 6, k = idx & 63;
    int u, g;
    if (n < 64){ u = n >> 1; g = n & 1; }
    else       { u = (n - 64) >> 1; g = 2 + (n & 1); }
    int col = g * 32 + u;
    float w = 0.f;
    if (k < 32)       w = Ui[k * 128 + col];
    else if (k == 32) w = Wi[col];
    else if (k == 33) w = bi[col];
    __half wh = __float2half(w);
    __half wl = __float2half(w - __half2float(wh));
    uint32_t off = SWZ((uint32_t)(n * 128 + k * 2));
    *(__half*)(g_btiles + off)         = wh;
    *(__half*)(g_btiles + 16384 + off) = wl;
}

// =====================================================================
// Inner LSTM via warp-level fp16 mma.sync (R11 version, 105us).
// 1024 blocks x 128 thr (4 warps), 64 rows/block. Warp w owns rows
// 16w..16w+15 (no block sync in loop). Per step: D[16x128] =
// A[16x48] x B[48x128], 3-product fp16 hi/lo split, full-offset SW128.
// =====================================================================
__global__ void __launch_bounds__(128, 4) inner_mma(
    const float* __restrict__ x,
    const float* __restrict__ Wo, const float* __restrict__ bo)
{
    extern __shared__ char smc[];
    const uint32_t sb = smem_to_u32(smc);
    const int tid  = threadIdx.x;
    const int wid  = tid >> 5;
    const int lane = tid & 31;
    const int q    = lane & 3;
    const int rr   = lane >> 2;            // 0..7
    const int wrow0 = wid * 16;            // warp's first local row (0..48)

    // --- copy prebuilt B tiles (32KB contiguous: BH then BL) ---
    {
        const uint4* src = (const uint4*)g_btiles;
        uint4* dst = (uint4*)(smc + OFF_BH);
        for (int i = tid; i < 2048; i += 128) dst[i] = src[i];
    }
    // --- zero A tiles (h0=0, pads=0): 16KB = 4096 u32 ---
    for (int i = tid; i < 4096; i += 128)
        ((uint32_t*)(smc + OFF_AH))[i] = 0u;
    // --- stage bo ---
    if (tid < 96) ((float*)(smc + OFF_BO))[tid] = bo[tid];
    __syncthreads();

    // --- loop-invariant ldmatrix addressing (FULL swizzle per (lane,kc)) ---
    const uint32_t aRow  = wrow0 + (lane & 15);
    const uint32_t aByte = (uint32_t)(lane >> 4) << 4;
    const uint32_t aMask = (aRow & 7) << 4;
    const uint32_t aBase = sb + OFF_AH + aRow * 128;
    uint32_t akOff[3];
    #pragma unroll
    for (int kc = 0; kc < 3; kc++)
        akOff[kc] = (aByte + 32u * kc) ^ aMask;    // < 128, exact SW128

    uint32_t bBase[8];
    uint32_t bkOff[3];
    {
        uint32_t nrow = ((uint32_t)(lane >> 4) << 3) + (lane & 7);
        uint32_t bbyte = ((uint32_t)((lane >> 3) & 1)) << 4;
        uint32_t bMask = (nrow & 7) << 4;
        #pragma unroll
        for (int np = 0; np < 8; np++)
            bBase[np] = sb + OFF_BH + (16 * np + nrow) * 128;
        #pragma unroll
        for (int kc = 0; kc < 3; kc++)
            bkOff[kc] = (bbyte + 32u * kc) ^ bMask;
    }
    const uint32_t xoff = SWZ((uint32_t)((wrow0 + (lane & 15)) * 128 + 64));

    const long grow = (long)blockIdx.x * 64 + wrow0 + (lane & 15);
    const float* xrow = x + grow * Sn;
    float xnext = __ldg(xrow);

    float cst[16];
    #pragma unroll
    for (int i = 0; i < 16; i++) cst[i] = 0.f;

    const int row0 = wrow0 + rr;
    const int row1 = row0 + 8;

    #pragma unroll 1
    for (int s = 0; s < Sn; s++){
        if (lane < 16){
            float xv = xnext;
            int sp = (s + 1 < Sn) ? s + 1 : s;
            xnext = __ldg(xrow + sp);
            __half xh = __float2half(xv);
            __half xl = __float2half(xv - __half2float(xh));
            uint32_t hi = (0x3C00u << 16) | (uint32_t)__half_as_ushort(xh);
            uint32_t lo = (uint32_t)__half_as_ushort(xl);
            *(uint32_t*)(smc + OFF_AH + xoff) = hi;
            *(uint32_t*)(smc + OFF_AL + xoff) = lo;
        }
        __syncwarp();

        uint32_t ah[3][4], al[3][4];
        #pragma unroll
        for (int kc = 0; kc < 3; kc++){
            LDSM4(ah[kc], aBase + akOff[kc]);
            LDSM4(al[kc], aBase + 8192 + akOff[kc]);
        }
        __syncwarp();

        #pragma unroll
        for (int npp = 0; npp < 4; npp++){
            float dIF0[4] = {0.f,0.f,0.f,0.f};
            float dIF1[4] = {0.f,0.f,0.f,0.f};
            float dGO0[4] = {0.f,0.f,0.f,0.f};
            float dGO1[4] = {0.f,0.f,0.f,0.f};
            #pragma unroll
            for (int kc = 0; kc < 3; kc++){
                uint32_t bIFh[4], bIFl[4], bGOh[4], bGOl[4];
                LDSM4(bIFh, bBase[npp]     + bkOff[kc]);
                LDSM4(bIFl, bBase[npp]     + 16384 + bkOff[kc]);
                LDSM4(bGOh, bBase[npp + 4] + bkOff[kc]);
                LDSM4(bGOl, bBase[npp + 4] + 16384 + bkOff[kc]);
                MMA_F16(dIF0, ah[kc], bIFh[0], bIFh[1]);
                MMA_F16(dIF0, ah[kc], bIFl[0], bIFl[1]);
                MMA_F16(dIF0, al[kc], bIFh[0], bIFh[1]);
                MMA_F16(dIF1, ah[kc], bIFh[2], bIFh[3]);
                MMA_F16(dIF1, ah[kc], bIFl[2], bIFl[3]);
                MMA_F16(dIF1, al[kc], bIFh[2], bIFh[3]);
                MMA_F16(dGO0, ah[kc], bGOh[0], bGOh[1]);
                MMA_F16(dGO0, ah[kc], bGOl[0], bGOl[1]);
                MMA_F16(dGO0, al[kc], bGOh[0], bGOh[1]);
                MMA_F16(dGO1, ah[kc], bGOh[2], bGOh[3]);
                MMA_F16(dGO1, ah[kc], bGOl[2], bGOl[3]);
                MMA_F16(dGO1, al[kc], bGOh[2], bGOh[3]);
            }
            const int vA = 8 * npp + q;
            const int vB = vA + 4;
            #pragma unroll
            for (int e = 0; e < 4; e++){
                const float* dif = (e < 2) ? dIF0 : dIF1;
                const float* dgo = (e < 2) ? dGO0 : dGO1;
                int half_ = (e & 1) * 2;
                float zi = dif[half_], zf = dif[half_ + 1];
                float zg = dgo[half_], zo = dgo[half_ + 1];
                float ii = sigt(zi), ff = sigt(zf);
                float gg = tanha(zg), oo = sigt(zo);
                float cv = ff * cst[npp * 4 + e] + ii * gg;
                cst[npp * 4 + e] = cv;
                float h = oo * tanha(cv);
                int v  = (e < 2) ? vA : vB;
                int rw = (e & 1) ? row1 : row0;
                uint32_t off = SWZ((uint32_t)(rw * 128 + v * 2));
                __half hh = __float2half(h);
                __half hl = __float2half(h - __half2float(hh));
                *(__half*)(smc + OFF_AH + off) = hh;
                *(__half*)(smc + OFF_AL + off) = hl;
            }
        }
        __syncwarp();
    }

    // --- zx epilogue: stage Wo (fp32) over the BH region, then GEMV ---
    __syncthreads();
    {
        float4* dst = (float4*)(smc + OFF_BH);
        const float4* src = (const float4*)Wo;   // 32*96 f32 = 768 float4
        for (int i = tid; i < 768; i += 128) dst[i] = src[i];
    }
    __syncthreads();
    {
        const int row = tid >> 1;          // 0..63
        const int cg  = tid & 1;
        const float* wos = (float*)(smc + OFF_BH);
        const float* bos = (float*)(smc + OFF_BO);
        float4 acc[12];
        #pragma unroll
        for (int j = 0; j < 12; j++)
            acc[j] = *(const float4*)(bos + cg * 48 + j * 4);
        #pragma unroll 4
        for (int k = 0; k < 32; k++){
            uint32_t off = SWZ((uint32_t)(row * 128 + k * 2));
            float hk = __half2float(*(__half*)(smc + OFF_AH + off))
                     + __half2float(*(__half*)(smc + OFF_AL + off));
            const float4* wp = (const float4*)(wos + k * 96 + cg * 48);
            #pragma unroll
            for (int j = 0; j < 12; j++){
                float4 w = wp[j];
                acc[j].x = fmaf(hk, w.x, acc[j].x);
                acc[j].y = fmaf(hk, w.y, acc[j].y);
                acc[j].z = fmaf(hk, w.z, acc[j].z);
                acc[j].w = fmaf(hk, w.w, acc[j].w);
            }
        }
        float* zp = g_zx + ((size_t)blockIdx.x * 64 + row) * 96 + cg * 48;
        #pragma unroll
        for (int j = 0; j < 12; j++) *(float4*)(zp + j * 4) = acc[j];
    }
}

// =====================================================================
// Outer LSTM + dense head: one warp per batch row. Register weights.
// h broadcast via DOUBLE-BUFFERED SMEM, stored pre-duplicated as (h,h)
// u64 -> 12 broadcast LDS.128 per step replace 24 SHFL + 24 pk2.
// One __syncwarp per step. Static depth-2 prefetch (R8 style).
// =====================================================================
__device__ __forceinline__ void outer_step_sm(
    float& h, float& c, u64 zA, u64 zB,
    const u64* hp, u64* hw, int l,
    const u64* w_if, const u64* w_go)
{
    const ulonglong2* hp2 = (const ulonglong2*)hp;
    u64 a0 = zA, a1 = 0ULL, b0 = zB, b1 = 0ULL;
    #pragma unroll
    for (int j = 0; j < 6; j++){
        ulonglong2 p = hp2[j];        // (h[2j],h[2j]), (h[2j+1],h[2j+1])
        ulonglong2 qq = hp2[j + 6];   // (h[12+2j],..), (h[13+2j],..)
        a0 = ffma2(p.x,  w_if[2*j],      a0);
        b0 = ffma2(p.x,  w_go[2*j],      b0);
        a0 = ffma2(p.y,  w_if[2*j + 1],  a0);
        b0 = ffma2(p.y,  w_go[2*j + 1],  b0);
        a1 = ffma2(qq.x, w_if[12 + 2*j], a1);
        b1 = ffma2(qq.x, w_go[12 + 2*j], b1);
        a1 = ffma2(qq.y, w_if[13 + 2*j], a1);
        b1 = ffma2(qq.y, w_go[13 + 2*j], b1);
    }
    u64 zAf = add2(a0, a1);
    u64 zBf = add2(b0, b1);
    float zi, zf, zg, zo;
    up2(zAf, zi, zf);
    up2(zBf, zg, zo);
    float fi = sigt(zi), ff = sigt(zf), gg = tanha(zg), oo = sigt(zo);
    c = fmaf(ff, c, fi * gg);
    h = oo * tanha(c);
    if (l < 24) hw[l] = pk2(h, h);   // duplicated store (STS.64)
    __syncwarp();
}

__global__ void __launch_bounds__(32) outer_kernel(
    const int*   __restrict__ lengths,
    const float* __restrict__ Uo,
    const float* __restrict__ Wd,
    const float* __restrict__ bd,
    float*       __restrict__ out)
{
    __shared__ __align__(16) u64 hsm[2][24];

    const int l  = threadIdx.x;
    const int la = (l < 24) ? l : 0;
    const int b  = blockIdx.x;

    u64 w_if[24], w_go[24];
    #pragma unroll
    for (int k = 0; k < 24; k++){
        const float* row = Uo + k * 96;
        w_if[k] = pk2(__ldg(row + la),      __ldg(row + 24 + la));
        w_go[k] = pk2(__ldg(row + 48 + la), __ldg(row + 72 + la));
    }

    const int len = lengths[b];            // in [1, T]
    const float* zr = g_zx + (size_t)b * Tn * 96;

    // static two-slot prefetch
    u64 A0, B0, A1, B1;
    A0 = pk2(zr[la], zr[24 + la]);
    B0 = pk2(zr[48 + la], zr[72 + la]);
    {
        const float* z1 = zr + ((len > 1) ? 96 : 0);
        A1 = pk2(z1[la], z1[24 + la]);
        B1 = pk2(z1[48 + la], z1[72 + la]);
    }

    if (l < 24) hsm[0][l] = 0ULL;          // h0 = 0 (duplicated)
    __syncwarp();

    float h = 0.f, c = 0.f;
    int t = 0;
    while (t < len){
        {   // even step: read buf0, write buf1
            u64 zA = A0, zB = B0;
            int tp = (t + 2 < len) ? t + 2 : len - 1;
            const float* zq = zr + (size_t)tp * 96;
            A0 = pk2(zq[la], zq[24 + la]);
            B0 = pk2(zq[48 + la], zq[72 + la]);
            outer_step_sm(h, c, zA, zB, hsm[0], hsm[1], l, w_if, w_go);
        }
        t++;
        if (t >= len) break;
        {   // odd step: read buf1, write buf0
            u64 zA = A1, zB = B1;
            int tp = (t + 2 < len) ? t + 2 : len - 1;
            const float* zq = zr + (size_t)tp * 96;
            A1 = pk2(zq[la], zq[24 + la]);
            B1 = pk2(zq[48 + la], zq[72 + la]);
            outer_step_sm(h, c, zA, zB, hsm[1], hsm[0], l, w_if, w_go);
        }
        t++;
    }

    // dense sigmoid head: out[b] = sigmoid(h . Wd + bd)
    float p = (l < 24) ? h * __ldg(Wd + la) : 0.f;
    #pragma unroll
    for (int off = 16; off; off >>= 1) p += __shfl_xor_sync(0xffffffffu, p, off);
    if (l == 0) out[b] = fmaf(0.5f, tanha(0.5f * (p + bd[0])), 0.5f);
}

extern "C" void kernel_launch(void* const* d_in, const int* in_sizes, int n_in,
                              void* d_out, int out_size)
{
    const float* x       = (const float*)d_in[0];
    const int*   lengths = (const int*)  d_in[1];
    const float* Wi      = (const float*)d_in[2];
    const float* Ui      = (const float*)d_in[3];
    const float* bi      = (const float*)d_in[4];
    const float* Wo      = (const float*)d_in[5];
    const float* Uo      = (const float*)d_in[6];
    const float* bo      = (const float*)d_in[7];
    const float* Wd      = (const float*)d_in[8];
    const float* bd      = (const float*)d_in[9];
    float* out = (float*)d_out;

    cudaFuncSetAttribute(inner_mma,
                         cudaFuncAttributeMaxDynamicSharedMemorySize, SMEM_SZ);

    bprep<<<32, 256>>>(Wi, Ui, bi);
    inner_mma<<<1024, 128, SMEM_SZ>>>(x, Wo, bo);
    outer_kernel<<<256, 32>>>(lengths, Uo, Wd, bd, out);
}

// round 14
// speedup vs baseline: 1.2795x; 1.1320x over previous
#include <cuda_runtime.h>
#include <cuda_fp16.h>
#include <cstdint>

typedef unsigned long long u64;

#define Bn 256
#define Tn 256
#define Sn 20
#define NROWS (Bn*Tn)   // 65536

__device__ float g_zx[NROWS * 96];   // zx[row][96] = h_inner[row] @ Wo + bo
__device__ __align__(16) unsigned char g_btiles[32768];  // Bh|Bl fp16, swizzled

// ---------- packed f32x2 helpers (outer kernel) ----------
__device__ __forceinline__ u64 ffma2(u64 a, u64 b, u64 c){
    u64 d;
    asm("fma.rn.f32x2 %0, %1, %2, %3;" : "=l"(d) : "l"(a), "l"(b), "l"(c));
    return d;
}
__device__ __forceinline__ u64 add2(u64 a, u64 b){
    u64 d;
    asm("add.rn.f32x2 %0, %1, %2;" : "=l"(d) : "l"(a), "l"(b));
    return d;
}
__device__ __forceinline__ u64 pk2(float lo, float hi){
    u64 r; asm("mov.b64 %0, {%1, %2};" : "=l"(r) : "f"(lo), "f"(hi)); return r;
}
__device__ __forceinline__ void up2(u64 v, float& lo, float& hi){
    asm("mov.b64 {%0, %1}, %2;" : "=f"(lo), "=f"(hi) : "l"(v));
}

// ---------- activations ----------
__device__ __forceinline__ float tanha(float x){
    float r; asm("tanh.approx.f32 %0, %1;" : "=f"(r) : "f"(x)); return r;
}
__device__ __forceinline__ float sigt(float x){
    return fmaf(0.5f, tanha(0.5f * x), 0.5f);
}

// ---------- smem / swizzle ----------
__device__ __forceinline__ uint32_t smem_to_u32(const void* p){
    uint32_t a;
    asm("{ .reg .u64 t; cvta.to.shared.u64 t, %1; cvt.u32.u64 %0, t; }"
        : "=r"(a) : "l"(p));
    return a;
}
#define SWZ(bo) ((bo) ^ (((bo) >> 3) & 0x70))

// ---------- mma.sync / ldmatrix (fp16, baseline PTX) ----------
#define MMA_F16(d, a, b0v, b1v) \
    asm volatile("mma.sync.aligned.m16n8k16.row.col.f32.f16.f16.f32 " \
        "{%0,%1,%2,%3}, {%4,%5,%6,%7}, {%8,%9}, {%0,%1,%2,%3};" \
        : "+f"((d)[0]), "+f"((d)[1]), "+f"((d)[2]), "+f"((d)[3]) \
        : "r"((a)[0]), "r"((a)[1]), "r"((a)[2]), "r"((a)[3]), "r"(b0v), "r"(b1v))

#define LDSM4(r, addr) \
    asm volatile("ldmatrix.sync.aligned.m8n8.x4.shared.b16 {%0,%1,%2,%3}, [%4];" \
        : "=r"((r)[0]), "=r"((r)[1]), "=r"((r)[2]), "=r"((r)[3]) : "r"(addr))

// SMEM layout (bytes)
#define OFF_AH 0        // A hi [64 rows][64 cols] fp16, 8KB (cols 0..31 = h)
#define OFF_AL 8192     // A lo, 8KB
#define OFF_BH 16384    // B hi [128][64] fp16, 16KB (Wo fp32 reused post-loop)
#define OFF_BL 32768    // B lo, 16KB
#define OFF_BO 49152    // bo, 96 f32 (384B)
#define OFF_WB 49536    // per-unit (w4,b4) Wi/bi table: 32 units x 32B = 1KB
#define OFF_XS 50560    // x staged [s][row]: 20 x 64 f32 = 5120B
#define SMEM_SZ 55680

// =====================================================================
// B-tile prep: loop-invariant weight tiles (fp16 hi/lo, SW128-swizzled).
// n-row = permuted gate col ([i,f]x32u | [g,o]x32u), k = Ui rows only
// (k>=32 entries written but never read since K=32 now).
// =====================================================================
__global__ void bprep(const float* __restrict__ Wi,
                      const float* __restrict__ Ui,
                      const float* __restrict__ bi)
{
    int idx = blockIdx.x * 256 + threadIdx.x;
    if (idx >= 8192) return;
    int n = idx >> 6, k = idx & 63;
    int u, g;
    if (n < 64){ u = n >> 1; g = n & 1; }
    else       { u = (n - 64) >> 1; g = 2 + (n & 1); }
    int col = g * 32 + u;
    float w = (k < 32) ? Ui[k * 128 + col] : 0.f;
    __half wh = __float2half(w);
    __half wl = __float2half(w - __half2float(wh));
    uint32_t off = SWZ((uint32_t)(n * 128 + k * 2));
    *(__half*)(g_btiles + off)         = wh;
    *(__half*)(g_btiles + 16384 + off) = wl;
}

// =====================================================================
// Inner LSTM via warp-level fp16 mma.sync. 1024 blocks x 128 thr (4 warps),
// 64 rows/block. Warp w owns rows 16w..16w+15 (no block sync in loop).
// R14: x*Wi + bi folded into the D-fragment INIT (fp32 FFMA from a 1KB
// per-unit table) -> K drops 48->32: MMA 144->96, LDSM 54->36 per step,
// and the fp16 x-split path is gone. h remains 3-product fp16 hi/lo.
// =====================================================================
__global__ void __launch_bounds__(128, 4) inner_mma(
    const float* __restrict__ x,  const float* __restrict__ Wi,
    const float* __restrict__ bi,
    const float* __restrict__ Wo, const float* __restrict__ bo)
{
    extern __shared__ char smc[];
    const uint32_t sb = smem_to_u32(smc);
    const int tid  = threadIdx.x;
    const int wid  = tid >> 5;
    const int lane = tid & 31;
    const int q    = lane & 3;
    const int rr   = lane >> 2;            // 0..7
    const int wrow0 = wid * 16;            // warp's first local row (0..48)

    // --- copy prebuilt B tiles (32KB contiguous: BH then BL) ---
    {
        const uint4* src = (const uint4*)g_btiles;
        uint4* dst = (uint4*)(smc + OFF_BH);
        for (int i = tid; i < 2048; i += 128) dst[i] = src[i];
    }
    // --- zero A tiles (h0=0, pads=0): 16KB = 4096 u32 ---
    for (int i = tid; i < 4096; i += 128)
        ((uint32_t*)(smc + OFF_AH))[i] = 0u;
    // --- stage bo ---
    if (tid < 96) ((float*)(smc + OFF_BO))[tid] = bo[tid];
    // --- per-unit (w4,b4) table: unit u -> Wi/bi at cols {u,32+u,64+u,96+u} ---
    if (tid < 32){
        int u = tid;
        float4 w4 = make_float4(Wi[u], Wi[32 + u], Wi[64 + u], Wi[96 + u]);
        float4 b4 = make_float4(bi[u], bi[32 + u], bi[64 + u], bi[96 + u]);
        *(float4*)(smc + OFF_WB + u * 32)      = w4;
        *(float4*)(smc + OFF_WB + u * 32 + 16) = b4;
    }
    // --- stage x transposed: xsm[s][row] (coalesced gmem reads) ---
    {
        const float* xg = x + (size_t)blockIdx.x * 64 * Sn;
        float* xsm = (float*)(smc + OFF_XS);
        for (int idx = tid; idx < 64 * Sn; idx += 128){
            int row = idx / Sn, s = idx % Sn;
            xsm[s * 64 + row] = xg[idx];
        }
    }
    __syncthreads();

    // --- loop-invariant ldmatrix addressing (FULL swizzle per (lane,kc)) ---
    const uint32_t aRow  = wrow0 + (lane & 15);
    const uint32_t aByte = (uint32_t)(lane >> 4) << 4;
    const uint32_t aMask = (aRow & 7) << 4;
    const uint32_t aBase = sb + OFF_AH + aRow * 128;
    uint32_t akOff[2];
    #pragma unroll
    for (int kc = 0; kc < 2; kc++)
        akOff[kc] = (aByte + 32u * kc) ^ aMask;

    uint32_t bBase[8];
    uint32_t bkOff[2];
    {
        uint32_t nrow = ((uint32_t)(lane >> 4) << 3) + (lane & 7);
        uint32_t bbyte = ((uint32_t)((lane >> 3) & 1)) << 4;
        uint32_t bMask = (nrow & 7) << 4;
        #pragma unroll
        for (int np = 0; np < 8; np++)
            bBase[np] = sb + OFF_BH + (16 * np + nrow) * 128;
        #pragma unroll
        for (int kc = 0; kc < 2; kc++)
            bkOff[kc] = (bbyte + 32u * kc) ^ bMask;
    }

    float cst[16];
    #pragma unroll
    for (int i = 0; i < 16; i++) cst[i] = 0.f;

    const int row0 = wrow0 + rr;
    const int row1 = row0 + 8;
    const float* xsm = (const float*)(smc + OFF_XS);

    #pragma unroll 1
    for (int s = 0; s < Sn; s++){
        float x0 = xsm[s * 64 + row0];
        float x1 = xsm[s * 64 + row1];

        uint32_t ah[2][4], al[2][4];
        #pragma unroll
        for (int kc = 0; kc < 2; kc++){
            LDSM4(ah[kc], aBase + akOff[kc]);
            LDSM4(al[kc], aBase + 8192 + akOff[kc]);
        }
        __syncwarp();   // A frags in regs before h overwrites below

        #pragma unroll
        for (int npp = 0; npp < 4; npp++){
            const int vA = 8 * npp + q;
            const int vB = vA + 4;
            float4 wA = *(const float4*)(smc + OFF_WB + vA * 32);
            float4 bA = *(const float4*)(smc + OFF_WB + vA * 32 + 16);
            float4 wB = *(const float4*)(smc + OFF_WB + vB * 32);
            float4 bB = *(const float4*)(smc + OFF_WB + vB * 32 + 16);
            // D init = x*Wi + bi (fp32): element map matches extraction below
            float dIF0[4] = { fmaf(x0, wA.x, bA.x), fmaf(x0, wA.y, bA.y),
                              fmaf(x1, wA.x, bA.x), fmaf(x1, wA.y, bA.y) };
            float dGO0[4] = { fmaf(x0, wA.z, bA.z), fmaf(x0, wA.w, bA.w),
                              fmaf(x1, wA.z, bA.z), fmaf(x1, wA.w, bA.w) };
            float dIF1[4] = { fmaf(x0, wB.x, bB.x), fmaf(x0, wB.y, bB.y),
                              fmaf(x1, wB.x, bB.x), fmaf(x1, wB.y, bB.y) };
            float dGO1[4] = { fmaf(x0, wB.z, bB.z), fmaf(x0, wB.w, bB.w),
                              fmaf(x1, wB.z, bB.z), fmaf(x1, wB.w, bB.w) };
            #pragma unroll
            for (int kc = 0; kc < 2; kc++){
                uint32_t bIFh[4], bIFl[4], bGOh[4], bGOl[4];
                LDSM4(bIFh, bBase[npp]     + bkOff[kc]);
                LDSM4(bIFl, bBase[npp]     + 16384 + bkOff[kc]);
                LDSM4(bGOh, bBase[npp + 4] + bkOff[kc]);
                LDSM4(bGOl, bBase[npp + 4] + 16384 + bkOff[kc]);
                MMA_F16(dIF0, ah[kc], bIFh[0], bIFh[1]);
                MMA_F16(dIF0, ah[kc], bIFl[0], bIFl[1]);
                MMA_F16(dIF0, al[kc], bIFh[0], bIFh[1]);
                MMA_F16(dIF1, ah[kc], bIFh[2], bIFh[3]);
                MMA_F16(dIF1, ah[kc], bIFl[2], bIFl[3]);
                MMA_F16(dIF1, al[kc], bIFh[2], bIFh[3]);
                MMA_F16(dGO0, ah[kc], bGOh[0], bGOh[1]);
                MMA_F16(dGO0, ah[kc], bGOl[0], bGOl[1]);
                MMA_F16(dGO0, al[kc], bGOh[0], bGOh[1]);
                MMA_F16(dGO1, ah[kc], bGOh[2], bGOh[3]);
                MMA_F16(dGO1, ah[kc], bGOl[2], bGOl[3]);
                MMA_F16(dGO1, al[kc], bGOh[2], bGOh[3]);
            }
            #pragma unroll
            for (int e = 0; e < 4; e++){
                const float* dif = (e < 2) ? dIF0 : dIF1;
                const float* dgo = (e < 2) ? dGO0 : dGO1;
                int half_ = (e & 1) * 2;
                float zi = dif[half_], zf = dif[half_ + 1];
                float zg = dgo[half_], zo = dgo[half_ + 1];
                float ii = sigt(zi), ff = sigt(zf);
                float gg = tanha(zg), oo = sigt(zo);
                float cv = ff * cst[npp * 4 + e] + ii * gg;
                cst[npp * 4 + e] = cv;
                float h = oo * tanha(cv);
                int v  = (e < 2) ? vA : vB;
                int rw = (e & 1) ? row1 : row0;
                uint32_t off = SWZ((uint32_t)(rw * 128 + v * 2));
                __half hh = __float2half(h);
                __half hl = __float2half(h - __half2float(hh));
                *(__half*)(smc + OFF_AH + off) = hh;
                *(__half*)(smc + OFF_AL + off) = hl;
            }
        }
        __syncwarp();   // h stores visible before next step's LDSM
    }

    // --- zx epilogue: stage Wo (fp32) over the BH region, then GEMV ---
    __syncthreads();
    {
        float4* dst = (float4*)(smc + OFF_BH);
        const float4* src = (const float4*)Wo;   // 32*96 f32 = 768 float4
        for (int i = tid; i < 768; i += 128) dst[i] = src[i];
    }
    __syncthreads();
    {
        const int row = tid >> 1;          // 0..63
        const int cg  = tid & 1;
        const float* wos = (float*)(smc + OFF_BH);
        const float* bos = (float*)(smc + OFF_BO);
        float4 acc[12];
        #pragma unroll
        for (int j = 0; j < 12; j++)
            acc[j] = *(const float4*)(bos + cg * 48 + j * 4);
        #pragma unroll 4
        for (int k = 0; k < 32; k++){
            uint32_t off = SWZ((uint32_t)(row * 128 + k * 2));
            float hk = __half2float(*(__half*)(smc + OFF_AH + off))
                     + __half2float(*(__half*)(smc + OFF_AL + off));
            const float4* wp = (const float4*)(wos + k * 96 + cg * 48);
            #pragma unroll
            for (int j = 0; j < 12; j++){
                float4 w = wp[j];
                acc[j].x = fmaf(hk, w.x, acc[j].x);
                acc[j].y = fmaf(hk, w.y, acc[j].y);
                acc[j].z = fmaf(hk, w.z, acc[j].z);
                acc[j].w = fmaf(hk, w.w, acc[j].w);
            }
        }
        float* zp = g_zx + ((size_t)blockIdx.x * 64 + row) * 96 + cg * 48;
        #pragma unroll
        for (int j = 0; j < 12; j++) *(float4*)(zp + j * 4) = acc[j];
    }
}

// =====================================================================
// Outer LSTM + dense head: one warp per batch row. Register weights.
// h broadcast via double-buffered SMEM (pre-duplicated (h,h) u64 ->
// 12 broadcast LDS.128 / step). Static depth-4 prefetch, 4x unrolled
// (named slots only, no dynamic indexing).
// =====================================================================
__device__ __forceinline__ void outer_step_sm(
    float& h, float& c, u64 zA, u64 zB,
    const u64* hp, u64* hw, int l,
    const u64* w_if, const u64* w_go)
{
    const ulonglong2* hp2 = (const ulonglong2*)hp;
    u64 a0 = zA, a1 = 0ULL, b0 = zB, b1 = 0ULL;
    #pragma unroll
    for (int j = 0; j < 6; j++){
        ulonglong2 p = hp2[j];
        ulonglong2 qq = hp2[j + 6];
        a0 = ffma2(p.x,  w_if[2*j],      a0);
        b0 = ffma2(p.x,  w_go[2*j],      b0);
        a0 = ffma2(p.y,  w_if[2*j + 1],  a0);
        b0 = ffma2(p.y,  w_go[2*j + 1],  b0);
        a1 = ffma2(qq.x, w_if[12 + 2*j], a1);
        b1 = ffma2(qq.x, w_go[12 + 2*j], b1);
        a1 = ffma2(qq.y, w_if[13 + 2*j], a1);
        b1 = ffma2(qq.y, w_go[13 + 2*j], b1);
    }
    u64 zAf = add2(a0, a1);
    u64 zBf = add2(b0, b1);
    float zi, zf, zg, zo;
    up2(zAf, zi, zf);
    up2(zBf, zg, zo);
    float fi = sigt(zi), ff = sigt(zf), gg = tanha(zg), oo = sigt(zo);
    c = fmaf(ff, c, fi * gg);
    h = oo * tanha(c);
    if (l < 24) hw[l] = pk2(h, h);
    __syncwarp();
}

__global__ void __launch_bounds__(32) outer_kernel(
    const int*   __restrict__ lengths,
    const float* __restrict__ Uo,
    const float* __restrict__ Wd,
    const float* __restrict__ bd,
    float*       __restrict__ out)
{
    __shared__ __align__(16) u64 hsm[2][24];

    const int l  = threadIdx.x;
    const int la = (l < 24) ? l : 0;
    const int b  = blockIdx.x;

    u64 w_if[24], w_go[24];
    #pragma unroll
    for (int k = 0; k < 24; k++){
        const float* row = Uo + k * 96;
        w_if[k] = pk2(__ldg(row + la),      __ldg(row + 24 + la));
        w_go[k] = pk2(__ldg(row + 48 + la), __ldg(row + 72 + la));
    }

    const int len = lengths[b];            // in [1, T]
    const float* zr = g_zx + (size_t)b * Tn * 96;

    // static depth-4 prefetch (named slots)
    u64 A0, B0, A1, B1, A2, B2, A3, B3;
    {
        int t1 = (1 < len) ? 1 : len - 1;
        int t2 = (2 < len) ? 2 : len - 1;
        int t3 = (3 < len) ? 3 : len - 1;
        const float* z0 = zr;
        const float* z1 = zr + (size_t)t1 * 96;
        const float* z2 = zr + (size_t)t2 * 96;
        const float* z3 = zr + (size_t)t3 * 96;
        A0 = pk2(z0[la], z0[24 + la]); B0 = pk2(z0[48 + la], z0[72 + la]);
        A1 = pk2(z1[la], z1[24 + la]); B1 = pk2(z1[48 + la], z1[72 + la]);
        A2 = pk2(z2[la], z2[24 + la]); B2 = pk2(z2[48 + la], z2[72 + la]);
        A3 = pk2(z3[la], z3[24 + la]); B3 = pk2(z3[48 + la], z3[72 + la]);
    }

    if (l < 24) hsm[0][l] = 0ULL;
    __syncwarp();

    float h = 0.f, c = 0.f;
    int t = 0;
    while (t < len){
        {   // step t (read buf0, write buf1)
            u64 zA = A0, zB = B0;
            int tp = (t + 4 < len) ? t + 4 : len - 1;
            const float* zq = zr + (size_t)tp * 96;
            A0 = pk2(zq[la], zq[24 + la]); B0 = pk2(zq[48 + la], zq[72 + la]);
            outer_step_sm(h, c, zA, zB, hsm[0], hsm[1], l, w_if, w_go);
        }
        if (++t >= len) break;
        {   // t+1 (buf1 -> buf0)
            u64 zA = A1, zB = B1;
            int tp = (t + 4 < len) ? t + 4 : len - 1;
            const float* zq = zr + (size_t)tp * 96;
            A1 = pk2(zq[la], zq[24 + la]); B1 = pk2(zq[48 + la], zq[72 + la]);
            outer_step_sm(h, c, zA, zB, hsm[1], hsm[0], l, w_if, w_go);
        }
        if (++t >= len) break;
        {   // t+2 (buf0 -> buf1)
            u64 zA = A2, zB = B2;
            int tp = (t + 4 < len) ? t + 4 : len - 1;
            const float* zq = zr + (size_t)tp * 96;
            A2 = pk2(zq[la], zq[24 + la]); B2 = pk2(zq[48 + la], zq[72 + la]);
            outer_step_sm(h, c, zA, zB, hsm[0], hsm[1], l, w_if, w_go);
        }
        if (++t >= len) break;
        {   // t+3 (buf1 -> buf0)
            u64 zA = A3, zB = B3;
            int tp = (t + 4 < len) ? t + 4 : len - 1;
            const float* zq = zr + (size_t)tp * 96;
            A3 = pk2(zq[la], zq[24 + la]); B3 = pk2(zq[48 + la], zq[72 + la]);
            outer_step_sm(h, c, zA, zB, hsm[1], hsm[0], l, w_if, w_go);
        }
        ++t;
    }

    // dense sigmoid head: out[b] = sigmoid(h . Wd + bd)
    float p = (l < 24) ? h * __ldg(Wd + la) : 0.f;
    #pragma unroll
    for (int off = 16; off; off >>= 1) p += __shfl_xor_sync(0xffffffffu, p, off);
    if (l == 0) out[b] = fmaf(0.5f, tanha(0.5f * (p + bd[0])), 0.5f);
}

extern "C" void kernel_launch(void* const* d_in, const int* in_sizes, int n_in,
                              void* d_out, int out_size)
{
    const float* x       = (const float*)d_in[0];
    const int*   lengths = (const int*)  d_in[1];
    const float* Wi      = (const float*)d_in[2];
    const float* Ui      = (const float*)d_in[3];
    const float* bi      = (const float*)d_in[4];
    const float* Wo      = (const float*)d_in[5];
    const float* Uo      = (const float*)d_in[6];
    const float* bo      = (const float*)d_in[7];
    const float* Wd      = (const float*)d_in[8];
    const float* bd      = (const float*)d_in[9];
    float* out = (float*)d_out;

    cudaFuncSetAttribute(inner_mma,
                         cudaFuncAttributeMaxDynamicSharedMemorySize, SMEM_SZ);

    bprep<<<32, 256>>>(Wi, Ui, bi);
    inner_mma<<<1024, 128, SMEM_SZ>>>(x, Wi, bi, Wo, bo);
    outer_kernel<<<256, 32>>>(lengths, Uo, Wd, bd, out);
}